// round 6
// baseline (speedup 1.0000x reference)
#include <cuda_runtime.h>
#include <cstdint>

// out[e, 0:128]   = X[src[e], :]
// out[e, 128:256] = X[dst[e], :]
// X: [N, 128] fp32 (row = 512 B)   indices: [E, 2] int32   out: [E, 256] fp32
//
// 16 chunks/thread as two software-pipelined batches of 8:
//   - all 16 warp-uniform idx loads issued first (batch1 idx latency hidden)
//   - gather+store batch0, then gather+store batch1 (v[] reused -> regs ~60)
// 32-bit byte addressing into X (51.2MB < 4GB) removes 64-bit IMAD chains.
// Evict-first stores keep the 328MB output stream from evicting X in L2.

#define HB 8          // half-batch
#define CPT (2*HB)    // chunks per thread

__global__ void __launch_bounds__(256) link_embed_gather_kernel(
    const char* __restrict__ Xb,        // byte pointer to X
    const int* __restrict__ idx,
    float4* __restrict__ out,
    int total_chunks)   // E * 64
{
    const int stride = gridDim.x * blockDim.x;
    const int t0 = blockIdx.x * blockDim.x + threadIdx.x;

    if (t0 + (CPT - 1) * stride < total_chunks) {
        // ---- fast path ----
        unsigned off[CPT];   // byte offset of gather source
        #pragma unroll
        for (int i = 0; i < CPT; i++) {
            int t = t0 + i * stride;
            int e = t >> 6;
            int half = (t >> 5) & 1;
            int node = __ldg(&idx[e * 2 + half]);            // warp-uniform
            off[i] = ((unsigned)node << 9) | ((unsigned)(t & 31) << 4);
        }

        float4 v[HB];
        // batch 0
        #pragma unroll
        for (int i = 0; i < HB; i++)
            v[i] = __ldg((const float4*)(Xb + off[i]));
        #pragma unroll
        for (int i = 0; i < HB; i++)
            __stcs(&out[t0 + i * stride], v[i]);
        // batch 1
        #pragma unroll
        for (int i = 0; i < HB; i++)
            v[i] = __ldg((const float4*)(Xb + off[HB + i]));
        #pragma unroll
        for (int i = 0; i < HB; i++)
            __stcs(&out[t0 + (HB + i) * stride], v[i]);
    } else {
        // ---- guarded tail (not taken at bench shape) ----
        #pragma unroll 4
        for (int i = 0; i < CPT; i++) {
            int t = t0 + i * stride;
            if (t < total_chunks) {
                int e = t >> 6;
                int half = (t >> 5) & 1;
                int node = __ldg(&idx[e * 2 + half]);
                unsigned off = ((unsigned)node << 9) | ((unsigned)(t & 31) << 4);
                __stcs(&out[t], __ldg((const float4*)(Xb + off)));
            }
        }
    }
}

extern "C" void kernel_launch(void* const* d_in, const int* in_sizes, int n_in,
                              void* d_out, int out_size)
{
    const char* Xb = (const char*)d_in[0];
    const int* idx = (const int*)d_in[1];
    float4* out = (float4*)d_out;

    int E = in_sizes[1] / 2;          // indices has E*2 int32 elements
    int total_chunks = E * 64;

    int threads = 256;
    int chunks_per_block = threads * CPT;
    int blocks = (total_chunks + chunks_per_block - 1) / chunks_per_block;
    link_embed_gather_kernel<<<blocks, threads>>>(Xb, idx, out, total_chunks);
}